// round 5
// baseline (speedup 1.0000x reference)
#include <cuda_runtime.h>
#include <cuda_bf16.h>

// Fixed shapes
#define H_DIM   1024
#define N_DIM   64
#define SEQ_L   2048
#define LHALF   1024               // l-range per block
#define CHUNK   32                 // l-values per (c, q) thread
#define NCH     (LHALF / CHUNK)    // 32 chunks per block

typedef unsigned long long ull;
__device__ __forceinline__ ull pack2(float lo, float hi) {
    ull r; asm("mov.b64 %0, {%1, %2};" : "=l"(r) : "f"(lo), "f"(hi)); return r;
}
__device__ __forceinline__ ull fma2(ull a, ull b, ull c) {
    ull d; asm("fma.rn.f32x2 %0, %1, %2, %3;" : "=l"(d) : "l"(a), "l"(b), "l"(c)); return d;
}
__device__ __forceinline__ ull mul2(ull a, ull b) {
    ull d; asm("mul.rn.f32x2 %0, %1, %2;" : "=l"(d) : "l"(a), "l"(b)); return d;
}
__device__ __forceinline__ ull add2(ull a, ull b) {
    ull d; asm("add.rn.f32x2 %0, %1, %2;" : "=l"(d) : "l"(a), "l"(b)); return d;
}

// ============================================================================
// One block per (h, l-half), 128 threads, 7 CTAs/SM pinned (2 full waves).
// Phase 1: threads (n, sub). Params per n; chunk seeds (y0,y1) marched with a
//          PACKED stride-32 order-2 recurrence (fma2+mul2 per chunk).
// Phase 2: threads (c, q). Packed stride-2 recurrence, 16 n per quarter.
// Phase 3: single-round balanced reduction: all publish [k][q][c], each warp
//          reduces and stores its own k-quarter.
// ============================================================================
__global__ void __launch_bounds__(128, 7) ssk_fused(
    const float* __restrict__ Cri, const float* __restrict__ logdt,
    const float* __restrict__ Bri, const float* __restrict__ invAr,
    const float* __restrict__ Aim, float* __restrict__ out)
{
    __shared__ float2 s_seed[N_DIM * NCH];   // 16KB, [n][c ^ (n&31)]
    __shared__ float4 s_par4[N_DIM];         // 1KB, (p2, p2, q2, q2) duplicated
    __shared__ float2 s_par1[N_DIM];         // 0.5KB, (p1, q1)

    const int tx   = threadIdx.x;            // 0..127
    const int h    = blockIdx.x >> 1;
    const int half = blockIdx.x & 1;

    // ---------------- Phase 1: params + packed seed march ----------------
    {
        const int n   = tx & 63;
        const int sub = tx >> 6;
        const int idx = h * N_DIM + n;
        const int nm  = n & 31;

        float cr = Cri[2 * idx], ci = Cri[2 * idx + 1];
        float br = Bri[2 * idx], bi = Bri[2 * idx + 1];
        float dt = __expf(logdt[h]);
        float Ar = -__expf(invAr[idx]);
        float Ai = Aim[idx];

        float zr = Ar * dt, zi = Ai * dt;
        float dr = 1.0f - 0.5f * zr, di = -0.5f * zi;
        float inv = 1.0f / (dr * dr + di * di);

        float bcr = br * cr - bi * ci;
        float bci = br * ci + bi * cr;
        float s = 2.0f * dt * inv;
        float ctr = (bcr * dr + bci * di) * s;   // Ct2 = 2*B*C*dt/den
        float cti = (bci * dr - bcr * di) * s;

        float nr = 1.0f + 0.5f * zr, ni = 0.5f * zi;
        float rr = (nr * dr + ni * di) * inv;    // r, |r| < 1
        float ri = (ni * dr - nr * di) * inv;

        float m2  = rr * rr + ri * ri;           // |r|^2
        float r2r = rr * rr - ri * ri;
        float r2i = 2.0f * rr * ri;
        if (sub == 0) {
            s_par4[n] = make_float4(2.0f * r2r, 2.0f * r2r,
                                    -(m2 * m2), -(m2 * m2));
            s_par1[n] = make_float2(2.0f * rr, -m2);
        }

        // s32 = r^32 : 4 squarings of r^2
        float sr = r2r, si = r2i;
#pragma unroll
        for (int i = 0; i < 4; i++) {
            float tr = sr * sr - si * si;
            si = 2.0f * sr * si;
            sr = tr;
        }
        const float p32 = 2.0f * sr;
        const float q32 = -(sr * sr + si * si);  // -|r^32|^2

        // w = Ct2 * r^(512*t), t = 2*half + sub
        float wr = ctr, wi = cti;
        const int t = 2 * half + sub;
        if (t) {
            float pr = sr, pi = si;              // -> r^512
#pragma unroll
            for (int i = 0; i < 4; i++) {
                float tr = pr * pr - pi * pi;
                pi = 2.0f * pr * pi;
                pr = tr;
            }
            float mr = pr, mi = pi;              // r^512
            if (t & 2) {
                float qr = pr * pr - pi * pi;    // r^1024
                float qi = 2.0f * pr * pi;
                if (t & 1) {                     // r^1536
                    float tr = qr * pr - qi * pi;
                    qi = qr * pi + qi * pr;
                    qr = tr;
                }
                mr = qr; mi = qi;
            }
            float tr = wr * mr - wi * mi;
            wi = wr * mi + wi * mr;
            wr = tr;
        }

        // First two chunk seeds: (Re w, Re w*r) and (Re w*s32, Re w*r*s32)
        float w1r  = wr * rr - wi * ri;
        float w1i  = wr * ri + wi * rr;
        float w32r = wr * sr - wi * si;
        float w33r = w1r * sr - w1i * si;

        const int cb = sub * 16;
        ull* sp = (ull*)s_seed + n * NCH;
        ull vP = pack2(wr, w1r);
        ull vC = pack2(w32r, w33r);
        sp[cb ^ nm]       = vP;
        sp[(cb + 1) ^ nm] = vC;

        const ull p32v = pack2(p32, p32);
        const ull q32v = pack2(q32, q32);
#pragma unroll
        for (int i = 2; i < 16; i++) {
            ull vN = fma2(p32v, vC, mul2(q32v, vP));
            sp[(cb + i) ^ nm] = vN;
            vP = vC; vC = vN;
        }
    }
    __syncthreads();

    // ---------------- Phase 2: packed recurrence ----------------
    const int c = tx & 31;                       // chunk (lane)
    const int q = tx >> 5;                       // quarter (warp)

    ull acc[CHUNK / 2];
#pragma unroll
    for (int k = 0; k < CHUNK / 2; k++) acc[k] = 0ull;

    const int n0 = q * 16;
#pragma unroll 1
    for (int np = 0; np < 8; np++) {
        const int na = n0 + 2 * np;
        const int nb = na + 1;

        ulonglong2 pqa = *((const ulonglong2*)&s_par4[na]);  // (p2,p2),(q2,q2)
        ulonglong2 pqb = *((const ulonglong2*)&s_par4[nb]);
        float2 ra = s_par1[na];                              // (p1, q1)
        float2 rb = s_par1[nb];
        float2 sa = s_seed[na * NCH + (c ^ (na & 31))];
        float2 sb = s_seed[nb * NCH + (c ^ (nb & 31))];

        // reconstruct y2, y3 via stride-1 recurrence
        float y2a = fmaf(ra.x, sa.y, ra.y * sa.x);
        float y3a = fmaf(ra.x, y2a, ra.y * sa.y);
        float y2b = fmaf(rb.x, sb.y, rb.y * sb.x);
        float y3b = fmaf(rb.x, y2b, rb.y * sb.y);

        ull vpA = pack2(sa.x, sa.y), vcA = pack2(y2a, y3a);
        ull vpB = pack2(sb.x, sb.y), vcB = pack2(y2b, y3b);

        acc[0] = add2(acc[0], add2(vpA, vpB));
        acc[1] = add2(acc[1], add2(vcA, vcB));

#pragma unroll
        for (int k = 2; k < CHUNK / 2; k++) {
            ull nA = fma2(pqa.x, vcA, mul2(pqa.y, vpA));
            ull nB = fma2(pqb.x, vcB, mul2(pqb.y, vpB));
            acc[k] = add2(acc[k], add2(nA, nB));
            vpA = vcA; vcA = nA;
            vpB = vcB; vcB = nB;
        }
    }

    // ------------- Phase 3: balanced single-round reduction -------------
    __syncthreads();                              // seeds no longer needed
    ull* red = (ull*)s_seed;                      // 16KB = 16k x 4q x 32c

#pragma unroll
    for (int k = 0; k < CHUNK / 2; k++)
        red[k * 128 + q * 32 + c] = acc[k];
    __syncthreads();

    // warp q reduces k in [4q, 4q+4) over quarters, stores 8 floats
    {
        const int kb = 4 * q;
        ull sum[4];
#pragma unroll
        for (int j = 0; j < 4; j++) {
            const int row = (kb + j) * 128 + c;
            sum[j] = add2(add2(red[row], red[row + 32]),
                          add2(red[row + 64], red[row + 96]));
        }
        ulonglong2* op = (ulonglong2*)(out + (size_t)h * SEQ_L
                                       + half * LHALF + c * CHUNK + 8 * q);
        op[0] = make_ulonglong2(sum[0], sum[1]);
        op[1] = make_ulonglong2(sum[2], sum[3]);
    }
}

extern "C" void kernel_launch(void* const* d_in, const int* in_sizes, int n_in,
                              void* d_out, int out_size)
{
    const float* Cri   = (const float*)d_in[0];   // (1, H, N, 2)
    const float* logdt = (const float*)d_in[1];   // (H,)
    const float* Bri   = (const float*)d_in[2];   // (H, N, 2) (n_ssm == H)
    const float* invAr = (const float*)d_in[3];   // (H, N)
    const float* Aim   = (const float*)d_in[4];   // (H, N)
    float* out = (float*)d_out;                   // (1, H, L)

    // ~17.5KB static + 12KB dummy dynamic -> ~29.5KB/CTA -> exactly 7 CTAs/SM,
    // conc = 1036 -> grid 2048 = 2 near-full waves.
    ssk_fused<<<H_DIM * 2, 128, 12 * 1024>>>(Cri, logdt, Bri, invAr, Aim, out);
}